// round 7
// baseline (speedup 1.0000x reference)
#include <cuda_runtime.h>

// out[row, :] = W[ids[row], :]
// W: [50257, 1024] fp32, ids: [32768] int32, out: [32768, 1024] fp32
// Software-pipelined gather: 16 rows per CTA, 2 rows per iteration
// (256 threads x 32B). Next iteration's gather issues BEFORE the current
// store waits on its load -> loads continuously in flight, no burst/drain
// duty cycle. 256-bit accesses with L2 eviction hints (weight sticky,
// output streaming).

struct V32 { unsigned long long a, b, c, d; };

__device__ __forceinline__ V32 ldg_evict_last(const V32* p) {
    V32 v;
    asm volatile("ld.global.nc.L2::evict_last.v4.b64 {%0,%1,%2,%3}, [%4];"
                 : "=l"(v.a), "=l"(v.b), "=l"(v.c), "=l"(v.d)
                 : "l"(p));
    return v;
}

__device__ __forceinline__ void stg_evict_first(V32* p, V32 v) {
    asm volatile("st.global.L2::evict_first.v4.b64 [%0], {%1,%2,%3,%4};"
                 :: "l"(p), "l"(v.a), "l"(v.b), "l"(v.c), "l"(v.d)
                 : "memory");
}

__global__ void __launch_bounds__(256)
embed_gather_kernel(const V32* __restrict__ w,
                    const int* __restrict__ ids,
                    V32* __restrict__ out)
{
    constexpr int ROWS_PER_CTA = 16;
    constexpr int ITERS = ROWS_PER_CTA / 2;     // 2 rows per iteration
    const int row0 = blockIdx.x * ROWS_PER_CTA;
    const int sub  = threadIdx.x >> 7;          // which row of the pair
    const int c    = threadIdx.x & 127;         // 32B chunk within row

    // Prologue: issue iteration 0's gather.
    int r = row0 + sub;
    long long id = (long long)ids[r];
    V32 cur = ldg_evict_last(w + id * 128 + c);

    // Steady state: issue load(i+1), then store(i) (which waits on load(i)).
    #pragma unroll 1
    for (int i = 1; i < ITERS; ++i) {
        const int rn = row0 + 2 * i + sub;
        const long long idn = (long long)ids[rn];
        V32 nxt = ldg_evict_last(w + idn * 128 + c);       // in flight early
        stg_evict_first(out + (long long)r * 128 + c, cur); // waits on cur
        cur = nxt;
        r = rn;
    }
    stg_evict_first(out + (long long)r * 128 + c, cur);
}

extern "C" void kernel_launch(void* const* d_in, const int* in_sizes, int n_in,
                              void* d_out, int out_size)
{
    // Resolve input order by element count: weight = 50257*1024, ids = 32768.
    int wi = 0, ii = 1;
    if (in_sizes[0] < in_sizes[1]) { wi = 1; ii = 0; }

    const V32* w    = (const V32*)d_in[wi];
    const int* ids  = (const int*)d_in[ii];
    const int n_rows = in_sizes[ii];            // 32768, divisible by 16

    V32* out = (V32*)d_out;
    embed_gather_kernel<<<n_rows / 16, 256>>>(w, ids, out);
}